// round 2
// baseline (speedup 1.0000x reference)
#include <cuda_runtime.h>
#include <math.h>
#include <stdint.h>

#define IMG 32
#define HDIM 1024
#define WDIM 1024
#define NBLK_X 128
#define NBLK_Y 128
#define LOSS_THR 120.0f

// ---- global scratch (no allocations allowed) ----
__device__ unsigned int g_max_enc;
__device__ unsigned int g_min_enc;

// order-preserving float<->uint encoding for atomic max/min
__device__ __forceinline__ unsigned int enc_f(float f) {
    unsigned int u = __float_as_uint(f);
    return (u & 0x80000000u) ? ~u : (u | 0x80000000u);
}
__device__ __forceinline__ float dec_f(unsigned int e) {
    unsigned int u = (e & 0x80000000u) ? (e ^ 0x80000000u) : ~e;
    return __uint_as_float(u);
}

__global__ void reset_kernel() {
    g_max_enc = 0x007FFFFFu;  // enc(-inf)
    g_min_enc = 0xFF800000u;  // enc(+inf)
}

// Phase A: global min/max of width-deltas xd = x - shift_right(x)
__global__ void minmax_kernel(const float* __restrict__ x) {
    const int n4 = (IMG * HDIM * WDIM) / 4;
    float vmax = -3.402823466e38f, vmin = 3.402823466e38f;
    for (int t = blockIdx.x * blockDim.x + threadIdx.x; t < n4;
         t += gridDim.x * blockDim.x) {
        float4 v = reinterpret_cast<const float4*>(x)[t];
        int e = t << 2;
        float left = ((e & (WDIM - 1)) == 0) ? 0.0f : __ldg(x + e - 1);
        float d0 = v.x - left;
        float d1 = v.y - v.x;
        float d2 = v.z - v.y;
        float d3 = v.w - v.z;
        vmax = fmaxf(fmaxf(fmaxf(d0, d1), fmaxf(d2, d3)), vmax);
        vmin = fminf(fminf(fminf(d0, d1), fminf(d2, d3)), vmin);
    }
    for (int o = 16; o; o >>= 1) {
        vmax = fmaxf(vmax, __shfl_xor_sync(0xFFFFFFFFu, vmax, o));
        vmin = fminf(vmin, __shfl_xor_sync(0xFFFFFFFFu, vmin, o));
    }
    __shared__ unsigned int smax, smin;
    if (threadIdx.x == 0) { smax = 0u; smin = 0xFFFFFFFFu; }
    __syncthreads();
    if ((threadIdx.x & 31) == 0) {
        atomicMax(&smax, enc_f(vmax));
        atomicMin(&smin, enc_f(vmin));
    }
    __syncthreads();
    if (threadIdx.x == 0) {
        atomicMax(&g_max_enc, smax);
        atomicMin(&g_min_enc, smin);
    }
}

// Phase B: one CTA per 8x8 spatial block (wb, hb); 32 images x 64 pixels.
__global__ __launch_bounds__(256) void block_kernel(const float* __restrict__ x,
                                                    float* __restrict__ out) {
    __shared__ float sd1[IMG][65];   // dequantized deltas d1[i][p] (+1 pad: kills bank conflicts)
    __shared__ float sxl[IMG][65];   // x_left[i][p]
    __shared__ float sbase[3][64];   // base = inv(AT_A) @ a_base
    __shared__ float sp[3][IMG];     // p[k][i]
    __shared__ float sS[5];          // S11 S12 S1 S22 S2
    __shared__ int   sdegen;
    __shared__ float smx, smn;

    const int tid = threadIdx.x;
    const int wb = blockIdx.x & (NBLK_X - 1);
    const int hb = blockIdx.x >> 7;

    if (tid == 0) {
        smx = dec_f(g_max_enc);
        smn = dec_f(g_min_enc);
    }
    __syncthreads();

    const float mx = smx, mn = smn;
    const bool neq = (mx != mn);
    const float scale = neq ? __fdiv_rn(65535.0f, __fsub_rn(mx, mn)) : 1.0f;
    const float s_inv = __fdiv_rn(1.0f, scale);
    const float m = neq ? mn : 0.0f;
    // lsb = 2^(round(log2(mx/2^15)) + 1): exact power of two
    const float lsb = exp2f(rintf(log2f(__fdiv_rn(mx, 32768.0f))) + 1.0f);
    const float rlsb = __fdiv_rn(1.0f, lsb);

    // ---- load + delta + quant-dequant (match reference op order, no FMA fusion) ----
    for (int idx = tid; idx < IMG * 64; idx += 256) {
        int i = idx >> 6;
        int p = idx & 63;
        int h = (hb << 3) + (p >> 3);
        int wc = (wb << 3) + (p & 7);
        int g = (i << 20) + (h << 10) + wc;
        float xv = x[g];
        float xl = (wc == 0) ? 0.0f : x[g - 1];
        float xd = __fsub_rn(xv, xl);
        float x1;
        if (neq) {
            float q = rintf(__fmul_rn(__fsub_rn(xd, mn), scale));
            x1 = __fadd_rn(__fmul_rn(q, s_inv), m);
        } else {
            x1 = xd;
        }
        sd1[i][p] = x1;
        sxl[i][p] = xl;
    }
    __syncthreads();

    // ---- Gram matrix of [a1; a2; 1] and degeneracy flags (warp 0) ----
    if (tid < 32) {
        float a1a = sd1[0][tid], a1b = sd1[0][tid + 32];
        float a2a = sd1[1][tid], a2b = sd1[1][tid + 32];
        float S11 = a1a * a1a + a1b * a1b;
        float S12 = a1a * a2a + a1b * a2b;
        float S1  = a1a + a1b;
        float S22 = a2a * a2a + a2b * a2b;
        float S2  = a2a + a2b;
        float mx1 = fmaxf(a1a, a1b), mn1 = fminf(a1a, a1b);
        float mx2 = fmaxf(a2a, a2b), mn2 = fminf(a2a, a2b);
        for (int o = 16; o; o >>= 1) {
            S11 += __shfl_xor_sync(0xFFFFFFFFu, S11, o);
            S12 += __shfl_xor_sync(0xFFFFFFFFu, S12, o);
            S1  += __shfl_xor_sync(0xFFFFFFFFu, S1, o);
            S22 += __shfl_xor_sync(0xFFFFFFFFu, S22, o);
            S2  += __shfl_xor_sync(0xFFFFFFFFu, S2, o);
            mx1 = fmaxf(mx1, __shfl_xor_sync(0xFFFFFFFFu, mx1, o));
            mn1 = fminf(mn1, __shfl_xor_sync(0xFFFFFFFFu, mn1, o));
            mx2 = fmaxf(mx2, __shfl_xor_sync(0xFFFFFFFFu, mx2, o));
            mn2 = fminf(mn2, __shfl_xor_sync(0xFFFFFFFFu, mn2, o));
        }
        if (tid == 0) {
            sS[0] = S11; sS[1] = S12; sS[2] = S1; sS[3] = S22; sS[4] = S2;
            sdegen = (((mx1 - mn1) < 1e-6f) && ((mx2 - mn2) < 1e-6f)) ? 1 : 0;
        }
    }
    __syncthreads();

    // ---- 3x3 symmetric inverse (redundant per-thread; registers only) ----
    const float A00 = sS[0], A01 = sS[1], A02 = sS[2];
    const float A11 = sS[3], A12 = sS[4], A22 = 64.0f;
    float det = A00 * (A11 * A22 - A12 * A12)
              - A01 * (A01 * A22 - A12 * A02)
              + A02 * (A01 * A12 - A11 * A02);
    float i00, i01, i02, i11, i12, i22;
    if (det == 0.0f) {   // reference: AT_A := eye(3) -> inv = eye
        i00 = 1.0f; i01 = 0.0f; i02 = 0.0f;
        i11 = 1.0f; i12 = 0.0f; i22 = 1.0f;
    } else {
        i00 = (A11 * A22 - A12 * A12) / det;
        i01 = (A02 * A12 - A01 * A22) / det;
        i02 = (A01 * A12 - A02 * A11) / det;
        i11 = (A00 * A22 - A02 * A02) / det;
        i12 = (A01 * A02 - A00 * A12) / det;
        i22 = (A00 * A11 - A01 * A01) / det;
    }

    // ---- base = inv @ a_base  (3 x 64) ----
    if (tid < 192) {
        int k = tid >> 6;
        int p = tid & 63;
        float c0 = (k == 0) ? i00 : ((k == 1) ? i01 : i02);
        float c1 = (k == 0) ? i01 : ((k == 1) ? i11 : i12);
        float c2 = (k == 0) ? i02 : ((k == 1) ? i12 : i22);
        sbase[k][p] = c0 * sd1[0][p] + c1 * sd1[1][p] + c2;
    }
    __syncthreads();

    // ---- p = base @ d  (3 x 32), 64-length dots ----
    if (tid < 96) {
        int k = tid >> 5;
        int i = tid & 31;
        float acc = 0.0f;
        #pragma unroll 8
        for (int p = 0; p < 64; p++)
            acc += sbase[k][p] * sd1[i][p];
        sp[k][i] = acc;
    }
    __syncthreads();

    // ---- reconstruct, quantize, loss gate, write output ----
    const int warp = tid >> 5;
    const int lane = tid & 31;
    const bool degen = (sdegen != 0);
    for (int ii = 0; ii < 4; ii++) {
        int i = (warp << 2) + ii;
        float p0 = sp[0][i], p1 = sp[1][i], p2 = sp[2][i];
        int pa = lane, pb = lane + 32;
        float ra = sd1[0][pa] * p0 + sd1[1][pa] * p1 + p2;
        float rb = sd1[0][pb] * p0 + sd1[1][pb] * p1 + p2;
        // lsb is a power of two: mul/round/mul are exact apart from the rint decision
        float r1a = __fmul_rn(rintf(__fmul_rn(ra, rlsb)), lsb);
        float r1b = __fmul_rn(rintf(__fmul_rn(rb, rlsb)), lsb);
        float da = sd1[i][pa] - r1a;
        float db = sd1[i][pb] - r1b;
        float loss = da * da + db * db;
        for (int o = 16; o; o >>= 1)
            loss += __shfl_xor_sync(0xFFFFFFFFu, loss, o);
        bool sel = (!degen) && (loss <= LOSS_THR);
        float rra = sel ? r1a : sd1[i][pa];
        float rrb = sel ? r1b : sd1[i][pb];
        int ha = (hb << 3) + (pa >> 3);
        int wa = (wb << 3) + (pa & 7);
        out[(i << 20) + (ha << 10) + wa] = __fadd_rn(rra, sxl[i][pa]);
        int hc = (hb << 3) + (pb >> 3);
        int wc = (wb << 3) + (pb & 7);
        out[(i << 20) + (hc << 10) + wc] = __fadd_rn(rrb, sxl[i][pb]);
    }
}

extern "C" void kernel_launch(void* const* d_in, const int* in_sizes, int n_in,
                              void* d_out, int out_size) {
    const float* x = (const float*)d_in[0];
    float* out = (float*)d_out;
    (void)in_sizes; (void)n_in; (void)out_size;

    reset_kernel<<<1, 1>>>();
    minmax_kernel<<<2048, 256>>>(x);
    block_kernel<<<NBLK_X * NBLK_Y, 256>>>(x, out);
}